// round 4
// baseline (speedup 1.0000x reference)
#include <cuda_runtime.h>

// FFF (fast feedforward) sparse tree-walk kernel, round 4.
// Inputs (metadata order):
//   d_in[0]: oldx  [8192, 768]  float32
//   d_in[1]: w_in  [4095, 768]  float32
//   d_in[2]: w_out [768, 4095]  float32
// Output: [8192, 768] float32
//
// Round-4: butterfly reduction restored (redux.f32 not on sm_100);
// dual-child L1 prefetch hides next-level load latency behind the reduce;
// gelu deferred out of the serial decision chain; launch_bounds(128,7).

#define FFF_B       8192
#define FFF_D       768
#define FFF_NODES   4095
#define FFF_DEPTH   11
#define FFF_LEVELS  (FFF_DEPTH + 1)      // 12 nodes on the path
#define FFF_ROW4    (FFF_D / 4)          // 192 float4 per 768-float row

// Transposed w_out scratch: [FFF_NODES, FFF_D] (node-major, coalesced rows).
__device__ float g_wout_t[(size_t)FFF_NODES * FFF_D];

// ---------------------------------------------------------------------------
// Tiled transpose: w_out [768, 4095] -> g_wout_t [4095, 768]
// ---------------------------------------------------------------------------
__global__ void fff_transpose_wout(const float* __restrict__ w_out) {
    __shared__ float tile[32][33];
    const int n0 = blockIdx.x * 32;   // node dim (4095)
    const int o0 = blockIdx.y * 32;   // output dim (768)

    const int n = n0 + threadIdx.x;
    #pragma unroll
    for (int j = 0; j < 4; j++) {
        const int o = o0 + threadIdx.y + j * 8;     // o < 768 always
        if (n < FFF_NODES) {
            tile[threadIdx.y + j * 8][threadIdx.x] = w_out[(size_t)o * FFF_NODES + n];
        }
    }
    __syncthreads();

    const int oo = o0 + threadIdx.x;                // always < 768
    #pragma unroll
    for (int j = 0; j < 4; j++) {
        const int nn = n0 + threadIdx.y + j * 8;
        if (nn < FFF_NODES) {
            g_wout_t[(size_t)nn * FFF_D + oo] = tile[threadIdx.x][threadIdx.y + j * 8];
        }
    }
}

__device__ __forceinline__ float fff_warp_sum(float v) {
    #pragma unroll
    for (int off = 16; off > 0; off >>= 1)
        v += __shfl_xor_sync(0xffffffffu, v, off);
    return v;
}

__device__ __forceinline__ void fff_prefetch_l1(const void* p) {
    asm volatile("prefetch.global.L1 [%0];" :: "l"(p));
}

// ---------------------------------------------------------------------------
// Main kernel: one warp per token.
// Phase 1: serial decision walk (logits only; gelu deferred), with
//          dual-child L1 prefetch overlapping the warp reduction.
// Phase 2: batch gelu, then 12 independent w_out row accumulations (MLP=12).
// ---------------------------------------------------------------------------
__global__ void __launch_bounds__(128, 7)
fff_walk_kernel(const float* __restrict__ x,
                const float* __restrict__ w_in,
                float* __restrict__ out) {
    const int warp = (int)((blockIdx.x * blockDim.x + threadIdx.x) >> 5);
    const int lane = threadIdx.x & 31;

    const float4* __restrict__ x4  = reinterpret_cast<const float4*>(x) + (size_t)warp * FFF_ROW4;
    const float4* __restrict__ wi4 = reinterpret_cast<const float4*>(w_in);
    const float4* __restrict__ wo4 = reinterpret_cast<const float4*>(g_wout_t);

    // Token's x row: 6 float4 per lane, lane-interleaved (coalesced).
    float4 xv[6];
    #pragma unroll
    for (int i = 0; i < 6; i++) xv[i] = x4[i * 32 + lane];

    // ---------------- Phase 1: serial decision walk ----------------
    float logits[FFF_LEVELS];
    unsigned cur = 0;
    #pragma unroll
    for (int d = 0; d < FFF_LEVELS; d++) {
        const float4* __restrict__ wr = wi4 + (size_t)cur * FFF_ROW4;
        float p0 = 0.f, p1 = 0.f, p2 = 0.f, p3 = 0.f;
        #pragma unroll
        for (int i = 0; i < 6; i += 2) {
            const float4 a = wr[i * 32 + lane];
            const float4 b = wr[(i + 1) * 32 + lane];
            p0 = fmaf(a.x, xv[i].x, p0);
            p1 = fmaf(a.y, xv[i].y, p1);
            p2 = fmaf(a.z, xv[i].z, p2);
            p3 = fmaf(a.w, xv[i].w, p3);
            p0 = fmaf(b.x, xv[i + 1].x, p0);
            p1 = fmaf(b.y, xv[i + 1].y, p1);
            p2 = fmaf(b.z, xv[i + 1].z, p2);
            p3 = fmaf(b.w, xv[i + 1].w, p3);
        }

        // Prefetch BOTH children's w_in rows into L1 while the reduction runs.
        // (Addresses depend only on cur, not on the pending decision.)
        if (d < FFF_LEVELS - 1) {
            const float4* c0 = wi4 + (size_t)(2u * cur + 1u) * FFF_ROW4;
            const float4* c1 = wi4 + (size_t)(2u * cur + 2u) * FFF_ROW4;
            #pragma unroll
            for (int i = 0; i < 6; i++) {
                fff_prefetch_l1(c0 + i * 32 + lane);
                fff_prefetch_l1(c1 + i * 32 + lane);
            }
        }

        const float p = fff_warp_sum((p0 + p1) + (p2 + p3));
        logits[d] = p;
        cur = 2u * cur + 1u + (p > 0.0f ? 1u : 0u);
    }
    // cur is now the level-12 "virtual" node; path node at level d is
    // ((cur+1) >> (12-d)) - 1  (ancestor chain of the final leaf).
    const unsigned vfinal = cur + 1u;

    // ---------------- Batch gelu (off the critical chain) ----------------
    float acts[FFF_LEVELS];
    #pragma unroll
    for (int d = 0; d < FFF_LEVELS; d++) {
        const float p = logits[d];
        // exact-erf gelu (matches jax.nn.gelu approximate=False)
        acts[d] = 0.5f * p * (1.0f + erff(p * 0.70710678118654752440f));
    }

    // ---------------- Phase 2: independent accumulation ----------------
    float4* __restrict__ o4 = reinterpret_cast<float4*>(out) + (size_t)warp * FFF_ROW4;
    #pragma unroll
    for (int i = 0; i < 6; i++) {
        const unsigned chunk = (unsigned)(i * 32 + lane);
        float a0 = 0.f, a1 = 0.f, a2 = 0.f, a3 = 0.f;
        #pragma unroll
        for (int d = 0; d < FFF_LEVELS; d++) {
            const unsigned node = (vfinal >> (FFF_LEVELS - d)) - 1u;
            const float4 w = wo4[node * (unsigned)FFF_ROW4 + chunk];  // 12 independent loads
            a0 = fmaf(acts[d], w.x, a0);
            a1 = fmaf(acts[d], w.y, a1);
            a2 = fmaf(acts[d], w.z, a2);
            a3 = fmaf(acts[d], w.w, a3);
        }
        o4[chunk] = make_float4(a0, a1, a2, a3);
    }
}

extern "C" void kernel_launch(void* const* d_in, const int* in_sizes, int n_in,
                              void* d_out, int out_size) {
    const float* x     = (const float*)d_in[0];
    const float* w_in  = (const float*)d_in[1];
    const float* w_out = (const float*)d_in[2];
    float* out = (float*)d_out;

    // 1) Transpose w_out into node-major scratch (coalesced both sides).
    {
        dim3 block(32, 8);
        dim3 grid((FFF_NODES + 31) / 32, FFF_D / 32);
        fff_transpose_wout<<<grid, block>>>(w_out);
    }

    // 2) Sparse tree walk: 4 warps (tokens) per 128-thread block.
    {
        const int threads = 128;
        const int blocks = FFF_B / 4;    // one warp per token
        fff_walk_kernel<<<blocks, threads>>>(x, w_in, out);
    }
}

// round 5
// speedup vs baseline: 1.2498x; 1.2498x over previous
#include <cuda_runtime.h>

// FFF (fast feedforward) sparse tree-walk kernel, round 5.
// Inputs (metadata order):
//   d_in[0]: oldx  [8192, 768]  float32
//   d_in[1]: w_in  [4095, 768]  float32
//   d_in[2]: w_out [768, 4095]  float32
// Output: [8192, 768] float32
//
// Round-5: prefetch reverted (doubled L2 traffic, clogged LSU — 61us FAIL).
// New: half-warp tokens — 16 lanes per token, 2 independent serial chains per
// warp (2x chain concurrency, 4-step reduction, zero extra traffic).

#define FFF_B       8192
#define FFF_D       768
#define FFF_NODES   4095
#define FFF_DEPTH   11
#define FFF_LEVELS  (FFF_DEPTH + 1)      // 12 nodes on the path
#define FFF_ROW4    (FFF_D / 4)          // 192 float4 per 768-float row
#define FFF_CHUNKS  (FFF_ROW4 / 16)      // 12 float4 per lane (16 lanes/token)

// Transposed w_out scratch: [FFF_NODES, FFF_D] (node-major, coalesced rows).
__device__ float g_wout_t[(size_t)FFF_NODES * FFF_D];

// ---------------------------------------------------------------------------
// Tiled transpose: w_out [768, 4095] -> g_wout_t [4095, 768]
// ---------------------------------------------------------------------------
__global__ void fff_transpose_wout(const float* __restrict__ w_out) {
    __shared__ float tile[32][33];
    const int n0 = blockIdx.x * 32;   // node dim (4095)
    const int o0 = blockIdx.y * 32;   // output dim (768)

    const int n = n0 + threadIdx.x;
    #pragma unroll
    for (int j = 0; j < 4; j++) {
        const int o = o0 + threadIdx.y + j * 8;     // o < 768 always
        if (n < FFF_NODES) {
            tile[threadIdx.y + j * 8][threadIdx.x] = w_out[(size_t)o * FFF_NODES + n];
        }
    }
    __syncthreads();

    const int oo = o0 + threadIdx.x;                // always < 768
    #pragma unroll
    for (int j = 0; j < 4; j++) {
        const int nn = n0 + threadIdx.y + j * 8;
        if (nn < FFF_NODES) {
            g_wout_t[(size_t)nn * FFF_D + oo] = tile[threadIdx.x][threadIdx.y + j * 8];
        }
    }
}

// Sum across a 16-lane half-warp (xor offsets stay inside the group).
__device__ __forceinline__ float fff_half_sum(float v) {
    #pragma unroll
    for (int off = 8; off > 0; off >>= 1)
        v += __shfl_xor_sync(0xffffffffu, v, off);
    return v;
}

// ---------------------------------------------------------------------------
// Main kernel: HALF-warp per token (2 tokens per warp, independent chains).
// Phase 1: serial decision walk (logits only; gelu deferred).
// Phase 2: batch gelu, then 12 independent w_out row accumulations (MLP=12).
// ---------------------------------------------------------------------------
__global__ void __launch_bounds__(128, 5)
fff_walk_kernel(const float* __restrict__ x,
                const float* __restrict__ w_in,
                float* __restrict__ out) {
    const int tid  = (int)(blockIdx.x * blockDim.x + threadIdx.x);
    const int warp = tid >> 5;
    const int lane = threadIdx.x & 31;
    const int sub  = lane & 15;               // lane within half-warp
    const int tok  = warp * 2 + (lane >> 4);  // token of this half-warp

    const float4* __restrict__ x4  = reinterpret_cast<const float4*>(x) + (size_t)tok * FFF_ROW4;
    const float4* __restrict__ wi4 = reinterpret_cast<const float4*>(w_in);
    const float4* __restrict__ wo4 = reinterpret_cast<const float4*>(g_wout_t);

    // Token's x row: 12 float4 per lane, 16-lane interleaved (coalesced 256B).
    float4 xv[FFF_CHUNKS];
    #pragma unroll
    for (int i = 0; i < FFF_CHUNKS; i++) xv[i] = x4[i * 16 + sub];

    // ---------------- Phase 1: serial decision walk ----------------
    float logits[FFF_LEVELS];
    unsigned cur = 0;   // uniform within each half-warp, differs between halves
    #pragma unroll
    for (int d = 0; d < FFF_LEVELS; d++) {
        const float4* __restrict__ wr = wi4 + (size_t)cur * FFF_ROW4;
        float p0 = 0.f, p1 = 0.f, p2 = 0.f, p3 = 0.f;
        #pragma unroll
        for (int i = 0; i < FFF_CHUNKS; i++) {
            const float4 a = wr[i * 16 + sub];
            p0 = fmaf(a.x, xv[i].x, p0);
            p1 = fmaf(a.y, xv[i].y, p1);
            p2 = fmaf(a.z, xv[i].z, p2);
            p3 = fmaf(a.w, xv[i].w, p3);
        }
        const float p = fff_half_sum((p0 + p1) + (p2 + p3));
        logits[d] = p;
        cur = 2u * cur + 1u + (p > 0.0f ? 1u : 0u);
    }
    // cur is now the level-12 "virtual" node; path node at level d is
    // ((cur+1) >> (12-d)) - 1  (ancestor chain of the final leaf).
    const unsigned vfinal = cur + 1u;

    // ---------------- Batch gelu (off the critical chain) ----------------
    float acts[FFF_LEVELS];
    #pragma unroll
    for (int d = 0; d < FFF_LEVELS; d++) {
        const float p = logits[d];
        // exact-erf gelu (matches jax.nn.gelu approximate=False)
        acts[d] = 0.5f * p * (1.0f + erff(p * 0.70710678118654752440f));
    }

    // ---------------- Phase 2: independent accumulation ----------------
    float4* __restrict__ o4 = reinterpret_cast<float4*>(out) + (size_t)tok * FFF_ROW4;
    #pragma unroll 4
    for (int i = 0; i < FFF_CHUNKS; i++) {
        const unsigned chunk = (unsigned)(i * 16 + sub);
        float a0 = 0.f, a1 = 0.f, a2 = 0.f, a3 = 0.f;
        #pragma unroll
        for (int d = 0; d < FFF_LEVELS; d++) {
            const unsigned node = (vfinal >> (FFF_LEVELS - d)) - 1u;
            const float4 w = wo4[node * (unsigned)FFF_ROW4 + chunk];  // 12 independent loads
            a0 = fmaf(acts[d], w.x, a0);
            a1 = fmaf(acts[d], w.y, a1);
            a2 = fmaf(acts[d], w.z, a2);
            a3 = fmaf(acts[d], w.w, a3);
        }
        o4[chunk] = make_float4(a0, a1, a2, a3);
    }
}

extern "C" void kernel_launch(void* const* d_in, const int* in_sizes, int n_in,
                              void* d_out, int out_size) {
    const float* x     = (const float*)d_in[0];
    const float* w_in  = (const float*)d_in[1];
    const float* w_out = (const float*)d_in[2];
    float* out = (float*)d_out;

    // 1) Transpose w_out into node-major scratch (coalesced both sides).
    {
        dim3 block(32, 8);
        dim3 grid((FFF_NODES + 31) / 32, FFF_D / 32);
        fff_transpose_wout<<<grid, block>>>(w_out);
    }

    // 2) Sparse tree walk: 2 tokens per warp, 4 warps per 128-thread block.
    {
        const int threads = 128;
        const int warps_total = FFF_B / 2;          // 4096 warps
        const int blocks = warps_total / 4;         // 1024 blocks
        fff_walk_kernel<<<blocks, threads>>>(x, w_in, out);
    }
}

// round 6
// speedup vs baseline: 1.5008x; 1.2008x over previous
#include <cuda_runtime.h>

// FFF (fast feedforward) sparse tree-walk kernel, round 6.
// Inputs (metadata order):
//   d_in[0]: oldx  [8192, 768]  float32
//   d_in[1]: w_in  [4095, 768]  float32
//   d_in[2]: w_out [768, 4095]  float32
// Output: [8192, 768] float32
//
// Round-6: revert to round-2 full-warp structure (best: 42.4us). Register
// diet: path logits distributed one-per-lane (lane d holds logit d), single
// gelu for all 12 levels, shfl broadcast in phase 2. launch_bounds(256,4)
// caps at 64 regs -> 32 warps/SM.

#define FFF_B       8192
#define FFF_D       768
#define FFF_NODES   4095
#define FFF_DEPTH   11
#define FFF_LEVELS  (FFF_DEPTH + 1)      // 12 nodes on the path
#define FFF_ROW4    (FFF_D / 4)          // 192 float4 per 768-float row

// Transposed w_out scratch: [FFF_NODES, FFF_D] (node-major, coalesced rows).
__device__ float g_wout_t[(size_t)FFF_NODES * FFF_D];

// ---------------------------------------------------------------------------
// Tiled transpose: w_out [768, 4095] -> g_wout_t [4095, 768]
// ---------------------------------------------------------------------------
__global__ void fff_transpose_wout(const float* __restrict__ w_out) {
    __shared__ float tile[32][33];
    const int n0 = blockIdx.x * 32;   // node dim (4095)
    const int o0 = blockIdx.y * 32;   // output dim (768)

    const int n = n0 + threadIdx.x;
    #pragma unroll
    for (int j = 0; j < 4; j++) {
        const int o = o0 + threadIdx.y + j * 8;     // o < 768 always
        if (n < FFF_NODES) {
            tile[threadIdx.y + j * 8][threadIdx.x] = w_out[(size_t)o * FFF_NODES + n];
        }
    }
    __syncthreads();

    const int oo = o0 + threadIdx.x;                // always < 768
    #pragma unroll
    for (int j = 0; j < 4; j++) {
        const int nn = n0 + threadIdx.y + j * 8;
        if (nn < FFF_NODES) {
            g_wout_t[(size_t)nn * FFF_D + oo] = tile[threadIdx.x][threadIdx.y + j * 8];
        }
    }
}

__device__ __forceinline__ float fff_warp_sum(float v) {
    #pragma unroll
    for (int off = 16; off > 0; off >>= 1)
        v += __shfl_xor_sync(0xffffffffu, v, off);
    return v;
}

// ---------------------------------------------------------------------------
// Main kernel: one warp per token.
// Phase 1: serial decision walk; lane d keeps logit d (1 reg of path state).
// Then ONE gelu covers all 12 levels (lanes 0..11).
// Phase 2: 6 chunk iterations, 12 independent gathered w_out loads each
// (MLP=12), act values broadcast from lanes via shfl.
// ---------------------------------------------------------------------------
__global__ void __launch_bounds__(256, 4)
fff_walk_kernel(const float* __restrict__ x,
                const float* __restrict__ w_in,
                float* __restrict__ out) {
    const int warp = (int)((blockIdx.x * blockDim.x + threadIdx.x) >> 5);
    const int lane = threadIdx.x & 31;

    const float4* __restrict__ x4  = reinterpret_cast<const float4*>(x) + (size_t)warp * FFF_ROW4;
    const float4* __restrict__ wi4 = reinterpret_cast<const float4*>(w_in);
    const float4* __restrict__ wo4 = reinterpret_cast<const float4*>(g_wout_t);

    // Token's x row: 6 float4 per lane, lane-interleaved (coalesced).
    float4 xv[6];
    #pragma unroll
    for (int i = 0; i < 6; i++) xv[i] = x4[i * 32 + lane];

    // ---------------- Phase 1: serial decision walk ----------------
    float mylogit = 0.f;   // lane d holds the level-d logit
    unsigned cur = 0;
    #pragma unroll
    for (int d = 0; d < FFF_LEVELS; d++) {
        const float4* __restrict__ wr = wi4 + (size_t)cur * FFF_ROW4;
        float p0 = 0.f, p1 = 0.f, p2 = 0.f, p3 = 0.f;
        #pragma unroll
        for (int i = 0; i < 6; i += 2) {
            const float4 a = wr[i * 32 + lane];
            const float4 b = wr[(i + 1) * 32 + lane];
            p0 = fmaf(a.x, xv[i].x, p0);
            p1 = fmaf(a.y, xv[i].y, p1);
            p2 = fmaf(a.z, xv[i].z, p2);
            p3 = fmaf(a.w, xv[i].w, p3);
            p0 = fmaf(b.x, xv[i + 1].x, p0);
            p1 = fmaf(b.y, xv[i + 1].y, p1);
            p2 = fmaf(b.z, xv[i + 1].z, p2);
            p3 = fmaf(b.w, xv[i + 1].w, p3);
        }
        const float p = fff_warp_sum((p0 + p1) + (p2 + p3));
        if (lane == d) mylogit = p;        // predicated select, 1 instr
        cur = 2u * cur + 1u + (p > 0.0f ? 1u : 0u);
    }
    // cur is now the level-12 "virtual" node; path node at level d is
    // ((cur+1) >> (12-d)) - 1  (ancestor chain of the final leaf).
    const unsigned vfinal = cur + 1u;

    // ---- ONE exact-erf gelu for all 12 levels (lane d -> act d) ----
    const float myact = 0.5f * mylogit *
                        (1.0f + erff(mylogit * 0.70710678118654752440f));

    // ---------------- Phase 2: independent accumulation ----------------
    float4* __restrict__ o4 = reinterpret_cast<float4*>(out) + (size_t)warp * FFF_ROW4;
    #pragma unroll
    for (int i = 0; i < 6; i++) {
        const unsigned chunk = (unsigned)(i * 32 + lane);
        float a0 = 0.f, a1 = 0.f, a2 = 0.f, a3 = 0.f;
        #pragma unroll
        for (int d = 0; d < FFF_LEVELS; d++) {
            const unsigned node = (vfinal >> (FFF_LEVELS - d)) - 1u;
            const float ad = __shfl_sync(0xffffffffu, myact, d);
            const float4 w = wo4[node * (unsigned)FFF_ROW4 + chunk];  // 12 independent loads
            a0 = fmaf(ad, w.x, a0);
            a1 = fmaf(ad, w.y, a1);
            a2 = fmaf(ad, w.z, a2);
            a3 = fmaf(ad, w.w, a3);
        }
        o4[chunk] = make_float4(a0, a1, a2, a3);
    }
}

extern "C" void kernel_launch(void* const* d_in, const int* in_sizes, int n_in,
                              void* d_out, int out_size) {
    const float* x     = (const float*)d_in[0];
    const float* w_in  = (const float*)d_in[1];
    const float* w_out = (const float*)d_in[2];
    float* out = (float*)d_out;

    // 1) Transpose w_out into node-major scratch (coalesced both sides).
    {
        dim3 block(32, 8);
        dim3 grid((FFF_NODES + 31) / 32, FFF_D / 32);
        fff_transpose_wout<<<grid, block>>>(w_out);
    }

    // 2) Sparse tree walk: one warp per token, 8 warps per 256-thread block.
    {
        const int threads = 256;
        const int blocks = FFF_B / 8;
        fff_walk_kernel<<<blocks, threads>>>(x, w_in, out);
    }
}